// round 11
// baseline (speedup 1.0000x reference)
#include <cuda_runtime.h>
#include <cstdint>

#define Bn 8
#define Cn 64
#define Hn 256
#define Wn 256
#define TM 64
#define NTH 512
#define NCH 16
#define NPAIR 8

// main-kernel smem byte offsets
#define XH_OFF 0          // x hi fp16 [64][256], swizzled rows (512B), 32KB
#define XL_OFF 32768      // x lo
#define B_OFF  65536      // 4-stage ring, 16KB/stage: {HI:[kh2][n256][k8], LO at +8192}
#define B_STAGE 16384
#define B_LO   8192
#define L_OFF  131072     // Ls f32 [64][256] swizzled, 64KB
#define R_OFF  196608     // red [64][8] f32
#define SM_TOTAL 198656

// Pre-split fp16 weight planes: [which(3)][c(64)][chunk(16)][16KB stage image]
__device__ __align__(16) char g_wsplit[3ULL * 64 * 16 * 16384];

__device__ __forceinline__ uint32_t f2h(float f) {
    uint32_t r; asm("cvt.rn.f16.f32 %0,%1;" : "=r"(r) : "f"(f)); return r;
}
__device__ __forceinline__ float h2f(uint32_t h) {
    float r; asm("cvt.f32.f16 %0,%1;" : "=f"(r) : "r"(h)); return r;
}
__device__ __forceinline__ void sts64(uint32_t a, uint32_t x, uint32_t y) {
    asm volatile("st.shared.v2.b32 [%0],{%1,%2};" :: "r"(a), "r"(x), "r"(y));
}
__device__ __forceinline__ void stsf2(uint32_t a, float x, float y) {
    asm volatile("st.shared.v2.f32 [%0],{%1,%2};" :: "r"(a), "f"(x), "f"(y));
}
__device__ __forceinline__ float2 ldsf2(uint32_t a) {
    float2 r;
    asm volatile("ld.shared.v2.f32 {%0,%1},[%2];" : "=f"(r.x), "=f"(r.y) : "r"(a));
    return r;
}
__device__ __forceinline__ void ldmx4(uint32_t* r, uint32_t a) {
    asm volatile("ldmatrix.sync.aligned.m8n8.x4.shared.b16 {%0,%1,%2,%3},[%4];"
                 : "=r"(r[0]), "=r"(r[1]), "=r"(r[2]), "=r"(r[3]) : "r"(a));
}
__device__ __forceinline__ void mma16(float* c, const uint32_t* a, uint32_t b0, uint32_t b1) {
    asm volatile(
        "mma.sync.aligned.m16n8k16.row.col.f32.f16.f16.f32 "
        "{%0,%1,%2,%3},{%4,%5,%6,%7},{%8,%9},{%0,%1,%2,%3};"
        : "+f"(c[0]), "+f"(c[1]), "+f"(c[2]), "+f"(c[3])
        : "r"(a[0]), "r"(a[1]), "r"(a[2]), "r"(a[3]), "r"(b0), "r"(b1));
}
__device__ __forceinline__ void cp_async16(uint32_t dst, const void* src) {
    asm volatile("cp.async.cg.shared.global [%0], [%1], 16;" :: "r"(dst), "l"(src));
}
__device__ __forceinline__ uint32_t ls_addr(uint32_t sm, int r, int cb, int m) {
    return sm + L_OFF + (uint32_t)(r * 1024) +
           (uint32_t)((((cb >> 3) ^ (r & 7)) << 5) + m * 8);
}

// ===========================================================================
// Weight pre-split kernel: W[c] fp32 [k][n] -> per-chunk stage image
//   hi[kh][n][j] fp16 at offset (kh*256+n)*16 + j*2 ; lo plane at +8192
// ===========================================================================
__global__ void __launch_bounds__(256) wsplit_kernel(
    const float* __restrict__ qw, const float* __restrict__ kw,
    const float* __restrict__ vw)
{
    __shared__ float tile[16][260];
    const int cc = blockIdx.x;         // chunk
    const int c  = blockIdx.y;         // channel
    const int z  = blockIdx.z;         // which weight
    const int tid = threadIdx.x;

    const float* wsrc = (z == 0) ? qw : (z == 1) ? kw : vw;
    const float* wp = wsrc + (size_t)c * Wn * Wn + (size_t)cc * 16 * Wn;

    #pragma unroll
    for (int i = 0; i < 4; ++i) {
        const int idx = tid + i * 256;          // float4 index over 16x256 tile
        const int r = idx >> 6, c4 = idx & 63;
        float4 v = reinterpret_cast<const float4*>(wp + (size_t)r * Wn)[c4];
        *reinterpret_cast<float4*>(&tile[r][c4 * 4]) = v;
    }
    __syncthreads();

    char* dst = g_wsplit + (((size_t)z * 64 + c) * 16 + cc) * 16384;
    #pragma unroll
    for (int i = 0; i < 4; ++i) {
        const int o = tid + i * 256;            // uint4 slot 0..1023
        const int plane = o >> 9, rem = o & 511;
        const int kh = rem >> 8, n = rem & 255;
        uint32_t w[4];
        #pragma unroll
        for (int q = 0; q < 4; ++q) {
            float f0 = tile[kh * 8 + 2 * q][n];
            float f1 = tile[kh * 8 + 2 * q + 1][n];
            uint32_t h0 = f2h(f0), h1 = f2h(f1);
            if (plane) {
                h0 = f2h(f0 - h2f(h0));
                h1 = f2h(f1 - h2f(h1));
            }
            w[q] = h0 | (h1 << 16);
        }
        reinterpret_cast<uint4*>(dst)[o] = make_uint4(w[0], w[1], w[2], w[3]);
    }
}

// ===========================================================================
// 64x256x256 GEMM, fp16 2-term split, pre-split weights via cp.async.
// 16 warps: wm in {0,1} (32 rows), wn in {0..7} (32 cols). acc[mt*16+nt*4+ci].
// Pair-structured mainloop: one barrier / one cp.async group per 2 chunks.
// ===========================================================================
__device__ __forceinline__ void gemm_f16(float acc[32], const char* __restrict__ ws_src,
                                         uint32_t sm, int tid, int lane, int wm, int wn)
{
    #pragma unroll
    for (int i = 0; i < 32; ++i) acc[i] = 0.f;

    auto ISSUE_PAIR = [&](int p) {          // chunks 2p, 2p+1 -> stages 2p&3, 2p+1&3
        #pragma unroll
        for (int h = 0; h < 2; ++h) {
            const int cc = 2 * p + h;
            const char* src = ws_src + (size_t)cc * 16384 + tid * 32;
            const uint32_t dst = sm + B_OFF + (uint32_t)((cc & 3) * B_STAGE + tid * 32);
            cp_async16(dst, src);
            cp_async16(dst + 16, src + 16);
        }
        asm volatile("cp.async.commit_group;");
    };

    ISSUE_PAIR(0);
    ISSUE_PAIR(1);

    const int li = lane >> 3, lj = lane & 7;
    const uint32_t ar0 = (uint32_t)(wm * 32 + (li & 1) * 8 + lj);
    const uint32_t bo = (uint32_t)((li & 1) * 4096 +
                        ((wn * 32) + ((li >> 1) * 8) + lj) * 16);

    #pragma unroll 1
    for (int p = 0; p < NPAIR; ++p) {
        if (p == 0) asm volatile("cp.async.wait_group 1;");
        else        asm volatile("cp.async.wait_group 0;");
        __syncthreads();
        if (p >= 1 && p + 1 < NPAIR) ISSUE_PAIR(p + 1);

        #pragma unroll
        for (int h = 0; h < 2; ++h) {
            const int cc = 2 * p + h;
            uint32_t ah[2][4], al[2][4];
            #pragma unroll
            for (int mt = 0; mt < 2; ++mt) {
                const uint32_t aoff = (ar0 + mt * 16) * 512 +
                    ((uint32_t)((cc * 2 + (li >> 1)) * 16) ^ (uint32_t)(lj * 16));
                ldmx4(ah[mt], sm + XH_OFF + aoff);
                ldmx4(al[mt], sm + XL_OFF + aoff);
            }
            uint32_t bh[8], bl[8];
            {
                const uint32_t bs = sm + B_OFF + (uint32_t)((cc & 3) * B_STAGE) + bo;
                ldmx4(&bh[0], bs);
                ldmx4(&bh[4], bs + 256);
                ldmx4(&bl[0], bs + B_LO);
                ldmx4(&bl[4], bs + B_LO + 256);
            }
            #pragma unroll
            for (int mt = 0; mt < 2; ++mt)
                #pragma unroll
                for (int nt = 0; nt < 4; ++nt) {
                    float* a4 = acc + mt * 16 + nt * 4;
                    mma16(a4, ah[mt], bh[nt * 2], bh[nt * 2 + 1]);
                    mma16(a4, ah[mt], bl[nt * 2], bl[nt * 2 + 1]);
                    mma16(a4, al[mt], bh[nt * 2], bh[nt * 2 + 1]);
                }
        }
    }
    __syncthreads();
}

extern __shared__ float smem_dyn[];

__global__ void __launch_bounds__(NTH, 1) axile_attn_f16(
    const float* __restrict__ x,
    const float* __restrict__ qb, const float* __restrict__ kb,
    const float* __restrict__ vb, float* __restrict__ out)
{
    const int tid  = threadIdx.x;
    const int lane = tid & 31;
    const int wid  = tid >> 5;
    const int wm   = wid & 1;
    const int wn   = wid >> 1;
    const int m    = lane & 3;
    const int g    = lane >> 2;
    const int ht   = blockIdx.x & 3;
    const int b    = blockIdx.x >> 2;
    const int c    = blockIdx.y;
    const int h0   = ht * TM;

    const uint32_t sm = (uint32_t)__cvta_generic_to_shared(smem_dyn);
    float* red = reinterpret_cast<float*>(reinterpret_cast<char*>(smem_dyn) + R_OFF);

    // ---- fill x fp16 hi/lo planes ----
    {
        const float* xg = x + ((size_t)((b * Cn + c) * Hn + h0)) * Wn;
        #pragma unroll
        for (int it = 0; it < 8; ++it) {
            const int idx = tid + it * NTH;
            const int r = idx >> 6, j4 = idx & 63, k = j4 * 4;
            float4 v = reinterpret_cast<const float4*>(xg)[(size_t)r * 64 + j4];
            const float f[4] = {v.x, v.y, v.z, v.w};
            uint32_t h[4], lo[4];
            #pragma unroll
            for (int s = 0; s < 4; ++s) {
                h[s]  = f2h(f[s]);
                lo[s] = f2h(f[s] - h2f(h[s]));
            }
            const uint32_t a = sm + XH_OFF + (uint32_t)(r * 512) +
                (((uint32_t)((k >> 3) * 16)) ^ ((uint32_t)((r & 7) * 16))) +
                (uint32_t)((k & 4) * 2);
            sts64(a,                     h[0]  | (h[1]  << 16), h[2]  | (h[3]  << 16));
            sts64(a + (XL_OFF - XH_OFF), lo[0] | (lo[1] << 16), lo[2] | (lo[3] << 16));
        }
    }
    // first gemm's first barrier covers x visibility

    const char* wq = g_wsplit + ((size_t)(0 * 64 + c)) * (16 * 16384);
    const char* wk = g_wsplit + ((size_t)(1 * 64 + c)) * (16 * 16384);
    const char* wv = g_wsplit + ((size_t)(2 * 64 + c)) * (16 * 16384);

    float acc[32];
    const int rAb = wm * 32 + g;              // + mt*16 (+8)
    const int cb0 = wn * 32;
    const size_t bias_row = ((size_t)c * Hn + h0) * Wn;

    // =============== Q gemm -> spill to Ls ===============
    gemm_f16(acc, wq, sm, tid, lane, wm, wn);
    #pragma unroll
    for (int mt = 0; mt < 2; ++mt)
        #pragma unroll
        for (int nt = 0; nt < 4; ++nt) {
            const int rA = rAb + mt * 16, rB = rA + 8;
            const int cb = cb0 + nt * 8;
            const float* a4 = acc + mt * 16 + nt * 4;
            stsf2(ls_addr(sm, rA, cb, m), a4[0], a4[1]);
            stsf2(ls_addr(sm, rB, cb, m), a4[2], a4[3]);
        }

    // =============== K gemm -> logits -> softmax -> P in Ls ===============
    gemm_f16(acc, wk, sm, tid, lane, wm, wn);
    {
        float mx[4] = {-3.4e38f, -3.4e38f, -3.4e38f, -3.4e38f};
        #pragma unroll
        for (int mt = 0; mt < 2; ++mt)
            #pragma unroll
            for (int nt = 0; nt < 4; ++nt) {
                const int rA = rAb + mt * 16, rB = rA + 8;
                const int cb = cb0 + nt * 8;
                float2 qA = ldsf2(ls_addr(sm, rA, cb, m));
                float2 qB = ldsf2(ls_addr(sm, rB, cb, m));
                const size_t ba = bias_row + (size_t)rA * Wn + cb + m * 2;
                const size_t bbo = bias_row + (size_t)rB * Wn + cb + m * 2;
                float2 bqA = *reinterpret_cast<const float2*>(qb + ba);
                float2 bqB = *reinterpret_cast<const float2*>(qb + bbo);
                float2 bkA = *reinterpret_cast<const float2*>(kb + ba);
                float2 bkB = *reinterpret_cast<const float2*>(kb + bbo);
                float* a4 = acc + mt * 16 + nt * 4;
                a4[0] = (qA.x + bqA.x) * (a4[0] + bkA.x);
                a4[1] = (qA.y + bqA.y) * (a4[1] + bkA.y);
                a4[2] = (qB.x + bqB.x) * (a4[2] + bkB.x);
                a4[3] = (qB.y + bqB.y) * (a4[3] + bkB.y);
                mx[mt * 2 + 0] = fmaxf(mx[mt * 2 + 0], fmaxf(a4[0], a4[1]));
                mx[mt * 2 + 1] = fmaxf(mx[mt * 2 + 1], fmaxf(a4[2], a4[3]));
            }
        #pragma unroll
        for (int q = 0; q < 4; ++q) {
            mx[q] = fmaxf(mx[q], __shfl_xor_sync(0xffffffffu, mx[q], 1));
            mx[q] = fmaxf(mx[q], __shfl_xor_sync(0xffffffffu, mx[q], 2));
        }
        if (m == 0) {
            #pragma unroll
            for (int q = 0; q < 4; ++q) {
                const int r = rAb + (q >> 1) * 16 + (q & 1) * 8;
                red[r * 8 + wn] = mx[q];
            }
        }
        __syncthreads();
        #pragma unroll
        for (int q = 0; q < 4; ++q) {
            const int r = rAb + (q >> 1) * 16 + (q & 1) * 8;
            float4 v0 = *reinterpret_cast<float4*>(&red[r * 8]);
            float4 v1 = *reinterpret_cast<float4*>(&red[r * 8 + 4]);
            mx[q] = fmaxf(fmaxf(fmaxf(v0.x, v0.y), fmaxf(v0.z, v0.w)),
                          fmaxf(fmaxf(v1.x, v1.y), fmaxf(v1.z, v1.w)));
        }
        __syncthreads();   // red reused for sums
        float sum[4] = {0.f, 0.f, 0.f, 0.f};
        #pragma unroll
        for (int mt = 0; mt < 2; ++mt)
            #pragma unroll
            for (int nt = 0; nt < 4; ++nt) {
                float* a4 = acc + mt * 16 + nt * 4;
                a4[0] = __expf(a4[0] - mx[mt * 2 + 0]); sum[mt * 2 + 0] += a4[0];
                a4[1] = __expf(a4[1] - mx[mt * 2 + 0]); sum[mt * 2 + 0] += a4[1];
                a4[2] = __expf(a4[2] - mx[mt * 2 + 1]); sum[mt * 2 + 1] += a4[2];
                a4[3] = __expf(a4[3] - mx[mt * 2 + 1]); sum[mt * 2 + 1] += a4[3];
            }
        #pragma unroll
        for (int q = 0; q < 4; ++q) {
            sum[q] += __shfl_xor_sync(0xffffffffu, sum[q], 1);
            sum[q] += __shfl_xor_sync(0xffffffffu, sum[q], 2);
        }
        if (m == 0) {
            #pragma unroll
            for (int q = 0; q < 4; ++q) {
                const int r = rAb + (q >> 1) * 16 + (q & 1) * 8;
                red[r * 8 + wn] = sum[q];
            }
        }
        __syncthreads();
        float rinv[4];
        #pragma unroll
        for (int q = 0; q < 4; ++q) {
            const int r = rAb + (q >> 1) * 16 + (q & 1) * 8;
            float4 v0 = *reinterpret_cast<float4*>(&red[r * 8]);
            float4 v1 = *reinterpret_cast<float4*>(&red[r * 8 + 4]);
            rinv[q] = 1.0f / (((v0.x + v0.y) + (v0.z + v0.w)) +
                              ((v1.x + v1.y) + (v1.z + v1.w)));
        }
        #pragma unroll
        for (int mt = 0; mt < 2; ++mt)
            #pragma unroll
            for (int nt = 0; nt < 4; ++nt) {
                const int rA = rAb + mt * 16, rB = rA + 8;
                const int cb = cb0 + nt * 8;
                float* a4 = acc + mt * 16 + nt * 4;
                stsf2(ls_addr(sm, rA, cb, m), a4[0] * rinv[mt * 2], a4[1] * rinv[mt * 2]);
                stsf2(ls_addr(sm, rB, cb, m), a4[2] * rinv[mt * 2 + 1], a4[3] * rinv[mt * 2 + 1]);
            }
    }

    // =============== V gemm -> out = P * (V + bv) ===============
    gemm_f16(acc, wv, sm, tid, lane, wm, wn);
    {
        float* og = out + ((size_t)((b * Cn + c) * Hn + h0)) * Wn;
        #pragma unroll
        for (int mt = 0; mt < 2; ++mt)
            #pragma unroll
            for (int nt = 0; nt < 4; ++nt) {
                const int rA = rAb + mt * 16, rB = rA + 8;
                const int cb = cb0 + nt * 8;
                float2 pA = ldsf2(ls_addr(sm, rA, cb, m));
                float2 pB = ldsf2(ls_addr(sm, rB, cb, m));
                const size_t ba = bias_row + (size_t)rA * Wn + cb + m * 2;
                const size_t bbo = bias_row + (size_t)rB * Wn + cb + m * 2;
                float2 bvA = *reinterpret_cast<const float2*>(vb + ba);
                float2 bvB = *reinterpret_cast<const float2*>(vb + bbo);
                const float* a4 = acc + mt * 16 + nt * 4;
                float2 oA, oB;
                oA.x = pA.x * (a4[0] + bvA.x);
                oA.y = pA.y * (a4[1] + bvA.y);
                oB.x = pB.x * (a4[2] + bvB.x);
                oB.y = pB.y * (a4[3] + bvB.y);
                *reinterpret_cast<float2*>(og + (size_t)rA * Wn + cb + m * 2) = oA;
                *reinterpret_cast<float2*>(og + (size_t)rB * Wn + cb + m * 2) = oB;
            }
    }
}

extern "C" void kernel_launch(void* const* d_in, const int* in_sizes, int n_in,
                              void* d_out, int out_size) {
    const float* x  = (const float*)d_in[0];
    const float* qw = (const float*)d_in[1];
    const float* kw = (const float*)d_in[2];
    const float* vw = (const float*)d_in[3];
    const float* qb = (const float*)d_in[4];
    const float* kb = (const float*)d_in[5];
    const float* vb = (const float*)d_in[6];
    float* out = (float*)d_out;

    // 1) pre-split weights into fp16 hi/lo stage images
    wsplit_kernel<<<dim3(16, 64, 3), 256>>>(qw, kw, vw);

    // 2) main fused kernel
    cudaFuncSetAttribute(axile_attn_f16,
                         cudaFuncAttributeMaxDynamicSharedMemorySize, SM_TOTAL);
    dim3 grid((Hn / TM) * Bn, Cn);   // 32 x 64 = 2048 CTAs
    axile_attn_f16<<<grid, NTH, SM_TOTAL>>>(x, qb, kb, vb, out);
}

// round 12
// speedup vs baseline: 1.0635x; 1.0635x over previous
#include <cuda_runtime.h>
#include <cstdint>

#define Bn 8
#define Cn 64
#define Hn 256
#define Wn 256
#define TM 64
#define NTH 512
#define NCH 16

// main-kernel smem byte offsets
#define XH_OFF 0          // x hi fp16 [64][256], swizzled rows (512B), 32KB
#define XL_OFF 32768      // x lo
#define B_OFF  65536      // 6-stage ring, 16KB/stage: {HI:[kh2][n256][k8], LO at +8192}
#define B_STAGE 16384
#define B_LO   8192
#define R_OFF  163840     // red [64][8] f32
#define SM_TOTAL 165888

// Pre-split fp16 weight planes: [which(3)][c(64)][chunk(16)][16KB stage image]
__device__ __align__(16) char g_wsplit[3ULL * 64 * 16 * 16384];

__device__ __forceinline__ uint32_t f2h(float f) {
    uint32_t r; asm("cvt.rn.f16.f32 %0,%1;" : "=r"(r) : "f"(f)); return r;
}
__device__ __forceinline__ float h2f(uint32_t h) {
    float r; asm("cvt.f32.f16 %0,%1;" : "=f"(r) : "r"(h)); return r;
}
__device__ __forceinline__ void sts64(uint32_t a, uint32_t x, uint32_t y) {
    asm volatile("st.shared.v2.b32 [%0],{%1,%2};" :: "r"(a), "r"(x), "r"(y));
}
__device__ __forceinline__ void ldmx4(uint32_t* r, uint32_t a) {
    asm volatile("ldmatrix.sync.aligned.m8n8.x4.shared.b16 {%0,%1,%2,%3},[%4];"
                 : "=r"(r[0]), "=r"(r[1]), "=r"(r[2]), "=r"(r[3]) : "r"(a));
}
__device__ __forceinline__ void mma16(float* c, const uint32_t* a, uint32_t b0, uint32_t b1) {
    asm volatile(
        "mma.sync.aligned.m16n8k16.row.col.f32.f16.f16.f32 "
        "{%0,%1,%2,%3},{%4,%5,%6,%7},{%8,%9},{%0,%1,%2,%3};"
        : "+f"(c[0]), "+f"(c[1]), "+f"(c[2]), "+f"(c[3])
        : "r"(a[0]), "r"(a[1]), "r"(a[2]), "r"(a[3]), "r"(b0), "r"(b1));
}
__device__ __forceinline__ void cp_async16(uint32_t dst, const void* src) {
    asm volatile("cp.async.cg.shared.global [%0], [%1], 16;" :: "r"(dst), "l"(src));
}

// ===========================================================================
// Weight pre-split kernel: W[c] fp32 [k][n] -> per-chunk stage image
// ===========================================================================
__global__ void __launch_bounds__(256) wsplit_kernel(
    const float* __restrict__ qw, const float* __restrict__ kw,
    const float* __restrict__ vw)
{
    __shared__ float tile[16][260];
    const int cc = blockIdx.x;
    const int c  = blockIdx.y;
    const int z  = blockIdx.z;
    const int tid = threadIdx.x;

    const float* wsrc = (z == 0) ? qw : (z == 1) ? kw : vw;
    const float* wp = wsrc + (size_t)c * Wn * Wn + (size_t)cc * 16 * Wn;

    #pragma unroll
    for (int i = 0; i < 4; ++i) {
        const int idx = tid + i * 256;
        const int r = idx >> 6, c4 = idx & 63;
        float4 v = reinterpret_cast<const float4*>(wp + (size_t)r * Wn)[c4];
        *reinterpret_cast<float4*>(&tile[r][c4 * 4]) = v;
    }
    __syncthreads();

    char* dst = g_wsplit + (((size_t)z * 64 + c) * 16 + cc) * 16384;
    #pragma unroll
    for (int i = 0; i < 4; ++i) {
        const int o = tid + i * 256;
        const int plane = o >> 9, rem = o & 511;
        const int kh = rem >> 8, n = rem & 255;
        uint32_t w[4];
        #pragma unroll
        for (int q = 0; q < 4; ++q) {
            float f0 = tile[kh * 8 + 2 * q][n];
            float f1 = tile[kh * 8 + 2 * q + 1][n];
            uint32_t h0 = f2h(f0), h1 = f2h(f1);
            if (plane) {
                h0 = f2h(f0 - h2f(h0));
                h1 = f2h(f1 - h2f(h1));
            }
            w[q] = h0 | (h1 << 16);
        }
        reinterpret_cast<uint4*>(dst)[o] = make_uint4(w[0], w[1], w[2], w[3]);
    }
}

// ===========================================================================
// Fused Q+K GEMM: shared A fragments, two B streams, 6-stage ring.
// Chunk cc occupies stages (2cc)%6 (Q) and (2cc+1)%6 (K).
// ===========================================================================
__device__ __forceinline__ void gemm_qk(float accQ[32], float accK[32],
                                        const char* __restrict__ wq,
                                        const char* __restrict__ wk,
                                        uint32_t sm, int tid, int lane, int wm, int wn)
{
    #pragma unroll
    for (int i = 0; i < 32; ++i) { accQ[i] = 0.f; accK[i] = 0.f; }

    auto ISSUE = [&](int cc) {
        #pragma unroll
        for (int s = 0; s < 2; ++s) {
            const char* src = (s ? wk : wq) + (size_t)cc * 16384 + tid * 32;
            const uint32_t dst = sm + B_OFF +
                (uint32_t)(((2 * cc + s) % 6) * B_STAGE + tid * 32);
            cp_async16(dst, src);
            cp_async16(dst + 16, src + 16);
        }
        asm volatile("cp.async.commit_group;");
    };

    ISSUE(0); ISSUE(1);

    const int li = lane >> 3, lj = lane & 7;
    const uint32_t ar0 = (uint32_t)(wm * 32 + (li & 1) * 8 + lj);
    const uint32_t bo = (uint32_t)((li & 1) * 4096 +
                        ((wn * 32) + ((li >> 1) * 8) + lj) * 16);

    #pragma unroll 1
    for (int cc = 0; cc < NCH; ++cc) {
        if (cc < NCH - 1) asm volatile("cp.async.wait_group 1;");
        else              asm volatile("cp.async.wait_group 0;");
        __syncthreads();
        if (cc + 2 < NCH) ISSUE(cc + 2);

        uint32_t ah[2][4], al[2][4];
        #pragma unroll
        for (int mt = 0; mt < 2; ++mt) {
            const uint32_t aoff = (ar0 + mt * 16) * 512 +
                ((uint32_t)((cc * 2 + (li >> 1)) * 16) ^ (uint32_t)(lj * 16));
            ldmx4(ah[mt], sm + XH_OFF + aoff);
            ldmx4(al[mt], sm + XL_OFF + aoff);
        }
        // ---- Q stream ----
        {
            uint32_t bh[8], bl[8];
            const uint32_t bs = sm + B_OFF +
                (uint32_t)(((2 * cc) % 6) * B_STAGE) + bo;
            ldmx4(&bh[0], bs);
            ldmx4(&bh[4], bs + 256);
            ldmx4(&bl[0], bs + B_LO);
            ldmx4(&bl[4], bs + B_LO + 256);
            #pragma unroll
            for (int mt = 0; mt < 2; ++mt)
                #pragma unroll
                for (int nt = 0; nt < 4; ++nt) {
                    float* a4 = accQ + mt * 16 + nt * 4;
                    mma16(a4, ah[mt], bh[nt * 2], bh[nt * 2 + 1]);
                    mma16(a4, ah[mt], bl[nt * 2], bl[nt * 2 + 1]);
                    mma16(a4, al[mt], bh[nt * 2], bh[nt * 2 + 1]);
                }
        }
        // ---- K stream ----
        {
            uint32_t bh[8], bl[8];
            const uint32_t bs = sm + B_OFF +
                (uint32_t)(((2 * cc + 1) % 6) * B_STAGE) + bo;
            ldmx4(&bh[0], bs);
            ldmx4(&bh[4], bs + 256);
            ldmx4(&bl[0], bs + B_LO);
            ldmx4(&bl[4], bs + B_LO + 256);
            #pragma unroll
            for (int mt = 0; mt < 2; ++mt)
                #pragma unroll
                for (int nt = 0; nt < 4; ++nt) {
                    float* a4 = accK + mt * 16 + nt * 4;
                    mma16(a4, ah[mt], bh[nt * 2], bh[nt * 2 + 1]);
                    mma16(a4, ah[mt], bl[nt * 2], bl[nt * 2 + 1]);
                    mma16(a4, al[mt], bh[nt * 2], bh[nt * 2 + 1]);
                }
        }
    }
    __syncthreads();
}

// ===========================================================================
// Single-stream V GEMM (R10 structure, stages mod 6).
// ===========================================================================
__device__ __forceinline__ void gemm_v(float acc[32], const char* __restrict__ wv,
                                       uint32_t sm, int tid, int lane, int wm, int wn)
{
    #pragma unroll
    for (int i = 0; i < 32; ++i) acc[i] = 0.f;

    auto ISSUE = [&](int cc) {
        const char* src = wv + (size_t)cc * 16384 + tid * 32;
        const uint32_t dst = sm + B_OFF + (uint32_t)((cc % 6) * B_STAGE + tid * 32);
        cp_async16(dst, src);
        cp_async16(dst + 16, src + 16);
        asm volatile("cp.async.commit_group;");
    };

    ISSUE(0); ISSUE(1); ISSUE(2);

    const int li = lane >> 3, lj = lane & 7;
    const uint32_t ar0 = (uint32_t)(wm * 32 + (li & 1) * 8 + lj);
    const uint32_t bo = (uint32_t)((li & 1) * 4096 +
                        ((wn * 32) + ((li >> 1) * 8) + lj) * 16);

    #pragma unroll 1
    for (int cc = 0; cc < NCH; ++cc) {
        if (cc < NCH - 2)       asm volatile("cp.async.wait_group 2;");
        else if (cc == NCH - 2) asm volatile("cp.async.wait_group 1;");
        else                    asm volatile("cp.async.wait_group 0;");
        __syncthreads();
        if (cc + 3 < NCH) ISSUE(cc + 3);

        uint32_t ah[2][4], al[2][4];
        #pragma unroll
        for (int mt = 0; mt < 2; ++mt) {
            const uint32_t aoff = (ar0 + mt * 16) * 512 +
                ((uint32_t)((cc * 2 + (li >> 1)) * 16) ^ (uint32_t)(lj * 16));
            ldmx4(ah[mt], sm + XH_OFF + aoff);
            ldmx4(al[mt], sm + XL_OFF + aoff);
        }
        uint32_t bh[8], bl[8];
        {
            const uint32_t bs = sm + B_OFF + (uint32_t)((cc % 6) * B_STAGE) + bo;
            ldmx4(&bh[0], bs);
            ldmx4(&bh[4], bs + 256);
            ldmx4(&bl[0], bs + B_LO);
            ldmx4(&bl[4], bs + B_LO + 256);
        }
        #pragma unroll
        for (int mt = 0; mt < 2; ++mt)
            #pragma unroll
            for (int nt = 0; nt < 4; ++nt) {
                float* a4 = acc + mt * 16 + nt * 4;
                mma16(a4, ah[mt], bh[nt * 2], bh[nt * 2 + 1]);
                mma16(a4, ah[mt], bl[nt * 2], bl[nt * 2 + 1]);
                mma16(a4, al[mt], bh[nt * 2], bh[nt * 2 + 1]);
            }
    }
    __syncthreads();
}

extern __shared__ float smem_dyn[];

__global__ void __launch_bounds__(NTH, 1) axile_attn_f16(
    const float* __restrict__ x,
    const float* __restrict__ qb, const float* __restrict__ kb,
    const float* __restrict__ vb, float* __restrict__ out)
{
    const int tid  = threadIdx.x;
    const int lane = tid & 31;
    const int wid  = tid >> 5;
    const int wm   = wid & 1;
    const int wn   = wid >> 1;
    const int m    = lane & 3;
    const int g    = lane >> 2;
    const int ht   = blockIdx.x & 3;
    const int b    = blockIdx.x >> 2;
    const int c    = blockIdx.y;
    const int h0   = ht * TM;

    const uint32_t sm = (uint32_t)__cvta_generic_to_shared(smem_dyn);
    float* red = reinterpret_cast<float*>(reinterpret_cast<char*>(smem_dyn) + R_OFF);

    // ---- fill x fp16 hi/lo planes ----
    {
        const float* xg = x + ((size_t)((b * Cn + c) * Hn + h0)) * Wn;
        #pragma unroll
        for (int it = 0; it < 8; ++it) {
            const int idx = tid + it * NTH;
            const int r = idx >> 6, j4 = idx & 63, k = j4 * 4;
            float4 v = reinterpret_cast<const float4*>(xg)[(size_t)r * 64 + j4];
            const float f[4] = {v.x, v.y, v.z, v.w};
            uint32_t h[4], lo[4];
            #pragma unroll
            for (int s = 0; s < 4; ++s) {
                h[s]  = f2h(f[s]);
                lo[s] = f2h(f[s] - h2f(h[s]));
            }
            const uint32_t a = sm + XH_OFF + (uint32_t)(r * 512) +
                (((uint32_t)((k >> 3) * 16)) ^ ((uint32_t)((r & 7) * 16))) +
                (uint32_t)((k & 4) * 2);
            sts64(a,                     h[0]  | (h[1]  << 16), h[2]  | (h[3]  << 16));
            sts64(a + (XL_OFF - XH_OFF), lo[0] | (lo[1] << 16), lo[2] | (lo[3] << 16));
        }
    }
    // first gemm's first barrier covers x visibility

    const char* wq = g_wsplit + ((size_t)(0 * 64 + c)) * (16 * 16384);
    const char* wk = g_wsplit + ((size_t)(1 * 64 + c)) * (16 * 16384);
    const char* wv = g_wsplit + ((size_t)(2 * 64 + c)) * (16 * 16384);

    float accQ[32], accK[32];
    const int rAb = wm * 32 + g;              // + mt*16 (+8)
    const int cb0 = wn * 32;
    const size_t bias_row = ((size_t)c * Hn + h0) * Wn;

    // =============== fused Q+K gemms ===============
    gemm_qk(accQ, accK, wq, wk, sm, tid, lane, wm, wn);

    // =============== logits -> softmax -> P (in accK) ===============
    {
        float mx[4] = {-3.4e38f, -3.4e38f, -3.4e38f, -3.4e38f};
        #pragma unroll
        for (int mt = 0; mt < 2; ++mt)
            #pragma unroll
            for (int nt = 0; nt < 4; ++nt) {
                const int rA = rAb + mt * 16, rB = rA + 8;
                const int cb = cb0 + nt * 8;
                const size_t ba  = bias_row + (size_t)rA * Wn + cb + m * 2;
                const size_t bbo = bias_row + (size_t)rB * Wn + cb + m * 2;
                float2 bqA = *reinterpret_cast<const float2*>(qb + ba);
                float2 bqB = *reinterpret_cast<const float2*>(qb + bbo);
                float2 bkA = *reinterpret_cast<const float2*>(kb + ba);
                float2 bkB = *reinterpret_cast<const float2*>(kb + bbo);
                float* qv = accQ + mt * 16 + nt * 4;
                float* kv = accK + mt * 16 + nt * 4;
                kv[0] = (qv[0] + bqA.x) * (kv[0] + bkA.x);
                kv[1] = (qv[1] + bqA.y) * (kv[1] + bkA.y);
                kv[2] = (qv[2] + bqB.x) * (kv[2] + bkB.x);
                kv[3] = (qv[3] + bqB.y) * (kv[3] + bkB.y);
                mx[mt * 2 + 0] = fmaxf(mx[mt * 2 + 0], fmaxf(kv[0], kv[1]));
                mx[mt * 2 + 1] = fmaxf(mx[mt * 2 + 1], fmaxf(kv[2], kv[3]));
            }
        #pragma unroll
        for (int q = 0; q < 4; ++q) {
            mx[q] = fmaxf(mx[q], __shfl_xor_sync(0xffffffffu, mx[q], 1));
            mx[q] = fmaxf(mx[q], __shfl_xor_sync(0xffffffffu, mx[q], 2));
        }
        if (m == 0) {
            #pragma unroll
            for (int q = 0; q < 4; ++q) {
                const int r = rAb + (q >> 1) * 16 + (q & 1) * 8;
                red[r * 8 + wn] = mx[q];
            }
        }
        __syncthreads();
        #pragma unroll
        for (int q = 0; q < 4; ++q) {
            const int r = rAb + (q >> 1) * 16 + (q & 1) * 8;
            float4 v0 = *reinterpret_cast<float4*>(&red[r * 8]);
            float4 v1 = *reinterpret_cast<float4*>(&red[r * 8 + 4]);
            mx[q] = fmaxf(fmaxf(fmaxf(v0.x, v0.y), fmaxf(v0.z, v0.w)),
                          fmaxf(fmaxf(v1.x, v1.y), fmaxf(v1.z, v1.w)));
        }
        __syncthreads();   // red reused for sums
        float sum[4] = {0.f, 0.f, 0.f, 0.f};
        #pragma unroll
        for (int mt = 0; mt < 2; ++mt)
            #pragma unroll
            for (int nt = 0; nt < 4; ++nt) {
                float* kv = accK + mt * 16 + nt * 4;
                kv[0] = __expf(kv[0] - mx[mt * 2 + 0]); sum[mt * 2 + 0] += kv[0];
                kv[1] = __expf(kv[1] - mx[mt * 2 + 0]); sum[mt * 2 + 0] += kv[1];
                kv[2] = __expf(kv[2] - mx[mt * 2 + 1]); sum[mt * 2 + 1] += kv[2];
                kv[3] = __expf(kv[3] - mx[mt * 2 + 1]); sum[mt * 2 + 1] += kv[3];
            }
        #pragma unroll
        for (int q = 0; q < 4; ++q) {
            sum[q] += __shfl_xor_sync(0xffffffffu, sum[q], 1);
            sum[q] += __shfl_xor_sync(0xffffffffu, sum[q], 2);
        }
        if (m == 0) {
            #pragma unroll
            for (int q = 0; q < 4; ++q) {
                const int r = rAb + (q >> 1) * 16 + (q & 1) * 8;
                red[r * 8 + wn] = sum[q];
            }
        }
        __syncthreads();
        float rinv[4];
        #pragma unroll
        for (int q = 0; q < 4; ++q) {
            const int r = rAb + (q >> 1) * 16 + (q & 1) * 8;
            float4 v0 = *reinterpret_cast<float4*>(&red[r * 8]);
            float4 v1 = *reinterpret_cast<float4*>(&red[r * 8 + 4]);
            rinv[q] = 1.0f / (((v0.x + v0.y) + (v0.z + v0.w)) +
                              ((v1.x + v1.y) + (v1.z + v1.w)));
        }
        #pragma unroll
        for (int mt = 0; mt < 2; ++mt)
            #pragma unroll
            for (int nt = 0; nt < 4; ++nt) {
                float* kv = accK + mt * 16 + nt * 4;
                kv[0] *= rinv[mt * 2];     kv[1] *= rinv[mt * 2];
                kv[2] *= rinv[mt * 2 + 1]; kv[3] *= rinv[mt * 2 + 1];
            }
        __syncthreads();   // red done before ring reuse in gemm_v
    }

    // =============== V gemm (acc reuses accQ) -> out = P * (V + bv) ===============
    gemm_v(accQ, wv, sm, tid, lane, wm, wn);
    {
        float* og = out + ((size_t)((b * Cn + c) * Hn + h0)) * Wn;
        #pragma unroll
        for (int mt = 0; mt < 2; ++mt)
            #pragma unroll
            for (int nt = 0; nt < 4; ++nt) {
                const int rA = rAb + mt * 16, rB = rA + 8;
                const int cb = cb0 + nt * 8;
                const size_t ba  = bias_row + (size_t)rA * Wn + cb + m * 2;
                const size_t bbo = bias_row + (size_t)rB * Wn + cb + m * 2;
                float2 bvA = *reinterpret_cast<const float2*>(vb + ba);
                float2 bvB = *reinterpret_cast<const float2*>(vb + bbo);
                const float* vv = accQ + mt * 16 + nt * 4;
                const float* pv = accK + mt * 16 + nt * 4;
                float2 oA, oB;
                oA.x = pv[0] * (vv[0] + bvA.x);
                oA.y = pv[1] * (vv[1] + bvA.y);
                oB.x = pv[2] * (vv[2] + bvB.x);
                oB.y = pv[3] * (vv[3] + bvB.y);
                *reinterpret_cast<float2*>(og + (size_t)rA * Wn + cb + m * 2) = oA;
                *reinterpret_cast<float2*>(og + (size_t)rB * Wn + cb + m * 2) = oB;
            }
    }
}

extern "C" void kernel_launch(void* const* d_in, const int* in_sizes, int n_in,
                              void* d_out, int out_size) {
    const float* x  = (const float*)d_in[0];
    const float* qw = (const float*)d_in[1];
    const float* kw = (const float*)d_in[2];
    const float* vw = (const float*)d_in[3];
    const float* qb = (const float*)d_in[4];
    const float* kb = (const float*)d_in[5];
    const float* vb = (const float*)d_in[6];
    float* out = (float*)d_out;

    // 1) pre-split weights into fp16 hi/lo stage images
    wsplit_kernel<<<dim3(16, 64, 3), 256>>>(qw, kw, vw);

    // 2) main fused kernel
    cudaFuncSetAttribute(axile_attn_f16,
                         cudaFuncAttributeMaxDynamicSharedMemorySize, SM_TOTAL);
    dim3 grid((Hn / TM) * Bn, Cn);   // 32 x 64 = 2048 CTAs
    axile_attn_f16<<<grid, NTH, SM_TOTAL>>>(x, qb, kb, vb, out);
}

// round 15
// speedup vs baseline: 1.3604x; 1.2792x over previous
#include <cuda_runtime.h>
#include <cstdint>

#define Bn 8
#define Cn 64
#define Hn 256
#define Wn 256
#define TM 32
#define NTH 256
#define NCH 16

// smem byte offsets (per CTA, 113KB total)
#define XH_OFF 0          // x hi fp16 [32][256], swizzled rows (512B), 16KB
#define XL_OFF 16384      // x lo
#define B_OFF  32768      // 3-stage ring, 16KB/stage: {HI:[kh2][n256][k8], LO at +8192}
#define B_STAGE 16384
#define B_LO   8192
#define L_OFF  81920      // Ls f32 [32][256] swizzled, 32KB
#define R_OFF  114688     // red [32][8] f32
#define SM_TOTAL 115712

// Pre-split fp16 weight planes: [which(3)][c(64)][chunk(16)][16KB stage image]
__device__ __align__(16) char g_wsplit[3ULL * 64 * 16 * 16384];

__device__ __forceinline__ uint32_t f2h(float f) {
    uint32_t r; asm("cvt.rn.f16.f32 %0,%1;" : "=r"(r) : "f"(f)); return r;
}
__device__ __forceinline__ float h2f(uint32_t h) {
    float r; asm("cvt.f32.f16 %0,%1;" : "=f"(r) : "r"(h)); return r;
}
__device__ __forceinline__ void sts64(uint32_t a, uint32_t x, uint32_t y) {
    asm volatile("st.shared.v2.b32 [%0],{%1,%2};" :: "r"(a), "r"(x), "r"(y));
}
__device__ __forceinline__ void stsf2(uint32_t a, float x, float y) {
    asm volatile("st.shared.v2.f32 [%0],{%1,%2};" :: "r"(a), "f"(x), "f"(y));
}
__device__ __forceinline__ float2 ldsf2(uint32_t a) {
    float2 r;
    asm volatile("ld.shared.v2.f32 {%0,%1},[%2];" : "=f"(r.x), "=f"(r.y) : "r"(a));
    return r;
}
__device__ __forceinline__ void ldmx4(uint32_t* r, uint32_t a) {
    asm volatile("ldmatrix.sync.aligned.m8n8.x4.shared.b16 {%0,%1,%2,%3},[%4];"
                 : "=r"(r[0]), "=r"(r[1]), "=r"(r[2]), "=r"(r[3]) : "r"(a));
}
__device__ __forceinline__ void mma16(float* c, const uint32_t* a, uint32_t b0, uint32_t b1) {
    asm volatile(
        "mma.sync.aligned.m16n8k16.row.col.f32.f16.f16.f32 "
        "{%0,%1,%2,%3},{%4,%5,%6,%7},{%8,%9},{%0,%1,%2,%3};"
        : "+f"(c[0]), "+f"(c[1]), "+f"(c[2]), "+f"(c[3])
        : "r"(a[0]), "r"(a[1]), "r"(a[2]), "r"(a[3]), "r"(b0), "r"(b1));
}
__device__ __forceinline__ void cp_async16(uint32_t dst, const void* src) {
    asm volatile("cp.async.cg.shared.global [%0], [%1], 16;" :: "r"(dst), "l"(src));
}
__device__ __forceinline__ uint32_t ls_addr(uint32_t sm, int r, int cb, int m) {
    return sm + L_OFF + (uint32_t)(r * 1024) +
           (uint32_t)((((cb >> 3) ^ (r & 7)) << 5) + m * 8);
}

// ===========================================================================
// Weight pre-split kernel: W[c] fp32 [k][n] -> per-chunk stage image
// ===========================================================================
__global__ void __launch_bounds__(256) wsplit_kernel(
    const float* __restrict__ qw, const float* __restrict__ kw,
    const float* __restrict__ vw)
{
    __shared__ float tile[16][260];
    const int cc = blockIdx.x;
    const int c  = blockIdx.y;
    const int z  = blockIdx.z;
    const int tid = threadIdx.x;

    const float* wsrc = (z == 0) ? qw : (z == 1) ? kw : vw;
    const float* wp = wsrc + (size_t)c * Wn * Wn + (size_t)cc * 16 * Wn;

    #pragma unroll
    for (int i = 0; i < 4; ++i) {
        const int idx = tid + i * 256;
        const int r = idx >> 6, c4 = idx & 63;
        float4 v = reinterpret_cast<const float4*>(wp + (size_t)r * Wn)[c4];
        *reinterpret_cast<float4*>(&tile[r][c4 * 4]) = v;
    }
    __syncthreads();

    char* dst = g_wsplit + (((size_t)z * 64 + c) * 16 + cc) * 16384;
    #pragma unroll
    for (int i = 0; i < 4; ++i) {
        const int o = tid + i * 256;
        const int plane = o >> 9, rem = o & 511;
        const int kh = rem >> 8, n = rem & 255;
        uint32_t w[4];
        #pragma unroll
        for (int q = 0; q < 4; ++q) {
            float f0 = tile[kh * 8 + 2 * q][n];
            float f1 = tile[kh * 8 + 2 * q + 1][n];
            uint32_t h0 = f2h(f0), h1 = f2h(f1);
            if (plane) {
                h0 = f2h(f0 - h2f(h0));
                h1 = f2h(f1 - h2f(h1));
            }
            w[q] = h0 | (h1 << 16);
        }
        reinterpret_cast<uint4*>(dst)[o] = make_uint4(w[0], w[1], w[2], w[3]);
    }
}

// ===========================================================================
// 32x256x256 GEMM, fp16 2-term split, 3-stage ring (depth-2 prefetch).
// 8 warps: wn = wid (32-col groups). Warp tile 32x32. acc[mt*16+nt*4+ci].
// ===========================================================================
__device__ __forceinline__ void gemm_f16(float acc[32], const char* __restrict__ ws_src,
                                         uint32_t sm, int tid, int lane, int wn)
{
    #pragma unroll
    for (int i = 0; i < 32; ++i) acc[i] = 0.f;

    auto ISSUE = [&](int cc) {
        const char* src = ws_src + (size_t)cc * 16384 + tid * 64;
        const uint32_t dst = sm + B_OFF + (uint32_t)((cc % 3) * B_STAGE + tid * 64);
        cp_async16(dst, src);
        cp_async16(dst + 16, src + 16);
        cp_async16(dst + 32, src + 32);
        cp_async16(dst + 48, src + 48);
        asm volatile("cp.async.commit_group;");
    };

    ISSUE(0); ISSUE(1);

    const int li = lane >> 3, lj = lane & 7;
    const uint32_t ar0 = (uint32_t)((li & 1) * 8 + lj);
    const uint32_t bo = (uint32_t)((li & 1) * 4096 +
                        ((wn * 32) + ((li >> 1) * 8) + lj) * 16);

    #pragma unroll 1
    for (int cc = 0; cc < NCH; ++cc) {
        if (cc < NCH - 1) asm volatile("cp.async.wait_group 1;");
        else              asm volatile("cp.async.wait_group 0;");
        __syncthreads();
        if (cc + 2 < NCH) ISSUE(cc + 2);

        uint32_t ah[2][4], al[2][4];
        #pragma unroll
        for (int mt = 0; mt < 2; ++mt) {
            const uint32_t aoff = (ar0 + mt * 16) * 512 +
                ((uint32_t)((cc * 2 + (li >> 1)) * 16) ^ (uint32_t)(lj * 16));
            ldmx4(ah[mt], sm + XH_OFF + aoff);
            ldmx4(al[mt], sm + XL_OFF + aoff);
        }
        uint32_t bh[8], bl[8];
        {
            const uint32_t bs = sm + B_OFF + (uint32_t)((cc % 3) * B_STAGE) + bo;
            ldmx4(&bh[0], bs);
            ldmx4(&bh[4], bs + 256);
            ldmx4(&bl[0], bs + B_LO);
            ldmx4(&bl[4], bs + B_LO + 256);
        }
        #pragma unroll
        for (int mt = 0; mt < 2; ++mt)
            #pragma unroll
            for (int nt = 0; nt < 4; ++nt) {
                float* a4 = acc + mt * 16 + nt * 4;
                mma16(a4, ah[mt], bh[nt * 2], bh[nt * 2 + 1]);
                mma16(a4, ah[mt], bl[nt * 2], bl[nt * 2 + 1]);
                mma16(a4, al[mt], bh[nt * 2], bh[nt * 2 + 1]);
            }
    }
    __syncthreads();
}

extern __shared__ float smem_dyn[];

__global__ void __launch_bounds__(NTH, 2) axile_attn_f16(
    const float* __restrict__ x,
    const float* __restrict__ qb, const float* __restrict__ kb,
    const float* __restrict__ vb, float* __restrict__ out)
{
    const int tid  = threadIdx.x;
    const int lane = tid & 31;
    const int wn   = tid >> 5;            // warp id = col group
    const int m    = lane & 3;
    const int g    = lane >> 2;
    const int ht   = blockIdx.x & 7;
    const int b    = blockIdx.x >> 3;
    const int c    = blockIdx.y;
    const int h0   = ht * TM;

    const uint32_t sm = (uint32_t)__cvta_generic_to_shared(smem_dyn);
    float* red = reinterpret_cast<float*>(reinterpret_cast<char*>(smem_dyn) + R_OFF);

    // ---- fill x fp16 hi/lo planes (32 rows) ----
    {
        const float* xg = x + ((size_t)((b * Cn + c) * Hn + h0)) * Wn;
        #pragma unroll
        for (int it = 0; it < 8; ++it) {
            const int idx = tid + it * NTH;
            const int r = idx >> 6, j4 = idx & 63, k = j4 * 4;
            float4 v = reinterpret_cast<const float4*>(xg)[(size_t)r * 64 + j4];
            const float f[4] = {v.x, v.y, v.z, v.w};
            uint32_t h[4], lo[4];
            #pragma unroll
            for (int s = 0; s < 4; ++s) {
                h[s]  = f2h(f[s]);
                lo[s] = f2h(f[s] - h2f(h[s]));
            }
            const uint32_t a = sm + XH_OFF + (uint32_t)(r * 512) +
                (((uint32_t)((k >> 3) * 16)) ^ ((uint32_t)((r & 7) * 16))) +
                (uint32_t)((k & 4) * 2);
            sts64(a,                     h[0]  | (h[1]  << 16), h[2]  | (h[3]  << 16));
            sts64(a + (XL_OFF - XH_OFF), lo[0] | (lo[1] << 16), lo[2] | (lo[3] << 16));
        }
    }
    // first gemm's first barrier covers x visibility

    const char* wq = g_wsplit + ((size_t)(0 * 64 + c)) * (16 * 16384);
    const char* wk = g_wsplit + ((size_t)(1 * 64 + c)) * (16 * 16384);
    const char* wv = g_wsplit + ((size_t)(2 * 64 + c)) * (16 * 16384);

    float acc[32];
    const int rAb = g;                    // rows: rAb + (q>>1)*16 + (q&1)*8
    const int cb0 = wn * 32;
    const size_t bias_row = ((size_t)c * Hn + h0) * Wn;

    // =============== Q gemm -> spill to Ls ===============
    gemm_f16(acc, wq, sm, tid, lane, wn);
    #pragma unroll
    for (int mt = 0; mt < 2; ++mt)
        #pragma unroll
        for (int nt = 0; nt < 4; ++nt) {
            const int rA = rAb + mt * 16, rB = rA + 8;
            const int cb = cb0 + nt * 8;
            const float* a4 = acc + mt * 16 + nt * 4;
            stsf2(ls_addr(sm, rA, cb, m), a4[0], a4[1]);
            stsf2(ls_addr(sm, rB, cb, m), a4[2], a4[3]);
        }

    // =============== K gemm -> logits -> softmax -> P in Ls ===============
    gemm_f16(acc, wk, sm, tid, lane, wn);
    {
        float mx[4] = {-3.4e38f, -3.4e38f, -3.4e38f, -3.4e38f};
        #pragma unroll
        for (int mt = 0; mt < 2; ++mt)
            #pragma unroll
            for (int nt = 0; nt < 4; ++nt) {
                const int rA = rAb + mt * 16, rB = rA + 8;
                const int cb = cb0 + nt * 8;
                float2 qA = ldsf2(ls_addr(sm, rA, cb, m));
                float2 qB = ldsf2(ls_addr(sm, rB, cb, m));
                const size_t ba  = bias_row + (size_t)rA * Wn + cb + m * 2;
                const size_t bbo = bias_row + (size_t)rB * Wn + cb + m * 2;
                float2 bqA = *reinterpret_cast<const float2*>(qb + ba);
                float2 bqB = *reinterpret_cast<const float2*>(qb + bbo);
                float2 bkA = *reinterpret_cast<const float2*>(kb + ba);
                float2 bkB = *reinterpret_cast<const float2*>(kb + bbo);
                float* a4 = acc + mt * 16 + nt * 4;
                a4[0] = (qA.x + bqA.x) * (a4[0] + bkA.x);
                a4[1] = (qA.y + bqA.y) * (a4[1] + bkA.y);
                a4[2] = (qB.x + bqB.x) * (a4[2] + bkB.x);
                a4[3] = (qB.y + bqB.y) * (a4[3] + bkB.y);
                mx[mt * 2 + 0] = fmaxf(mx[mt * 2 + 0], fmaxf(a4[0], a4[1]));
                mx[mt * 2 + 1] = fmaxf(mx[mt * 2 + 1], fmaxf(a4[2], a4[3]));
            }
        #pragma unroll
        for (int q = 0; q < 4; ++q) {
            mx[q] = fmaxf(mx[q], __shfl_xor_sync(0xffffffffu, mx[q], 1));
            mx[q] = fmaxf(mx[q], __shfl_xor_sync(0xffffffffu, mx[q], 2));
        }
        if (m == 0) {
            #pragma unroll
            for (int q = 0; q < 4; ++q) {
                const int r = rAb + (q >> 1) * 16 + (q & 1) * 8;
                red[r * 8 + wn] = mx[q];
            }
        }
        __syncthreads();
        #pragma unroll
        for (int q = 0; q < 4; ++q) {
            const int r = rAb + (q >> 1) * 16 + (q & 1) * 8;
            float4 v0 = *reinterpret_cast<float4*>(&red[r * 8]);
            float4 v1 = *reinterpret_cast<float4*>(&red[r * 8 + 4]);
            mx[q] = fmaxf(fmaxf(fmaxf(v0.x, v0.y), fmaxf(v0.z, v0.w)),
                          fmaxf(fmaxf(v1.x, v1.y), fmaxf(v1.z, v1.w)));
        }
        __syncthreads();   // red reused for sums
        float sum[4] = {0.f, 0.f, 0.f, 0.f};
        #pragma unroll
        for (int mt = 0; mt < 2; ++mt)
            #pragma unroll
            for (int nt = 0; nt < 4; ++nt) {
                float* a4 = acc + mt * 16 + nt * 4;
                a4[0] = __expf(a4[0] - mx[mt * 2 + 0]); sum[mt * 2 + 0] += a4[0];
                a4[1] = __expf(a4[1] - mx[mt * 2 + 0]); sum[mt * 2 + 0] += a4[1];
                a4[2] = __expf(a4[2] - mx[mt * 2 + 1]); sum[mt * 2 + 1] += a4[2];
                a4[3] = __expf(a4[3] - mx[mt * 2 + 1]); sum[mt * 2 + 1] += a4[3];
            }
        #pragma unroll
        for (int q = 0; q < 4; ++q) {
            sum[q] += __shfl_xor_sync(0xffffffffu, sum[q], 1);
            sum[q] += __shfl_xor_sync(0xffffffffu, sum[q], 2);
        }
        if (m == 0) {
            #pragma unroll
            for (int q = 0; q < 4; ++q) {
                const int r = rAb + (q >> 1) * 16 + (q & 1) * 8;
                red[r * 8 + wn] = sum[q];
            }
        }
        __syncthreads();
        float rinv[4];
        #pragma unroll
        for (int q = 0; q < 4; ++q) {
            const int r = rAb + (q >> 1) * 16 + (q & 1) * 8;
            float4 v0 = *reinterpret_cast<float4*>(&red[r * 8]);
            float4 v1 = *reinterpret_cast<float4*>(&red[r * 8 + 4]);
            rinv[q] = 1.0f / (((v0.x + v0.y) + (v0.z + v0.w)) +
                              ((v1.x + v1.y) + (v1.z + v1.w)));
        }
        #pragma unroll
        for (int mt = 0; mt < 2; ++mt)
            #pragma unroll
            for (int nt = 0; nt < 4; ++nt) {
                const int rA = rAb + mt * 16, rB = rA + 8;
                const int cb = cb0 + nt * 8;
                float* a4 = acc + mt * 16 + nt * 4;
                stsf2(ls_addr(sm, rA, cb, m), a4[0] * rinv[mt * 2], a4[1] * rinv[mt * 2]);
                stsf2(ls_addr(sm, rB, cb, m), a4[2] * rinv[mt * 2 + 1], a4[3] * rinv[mt * 2 + 1]);
            }
    }

    // =============== V gemm -> out = P * (V + bv) ===============
    gemm_f16(acc, wv, sm, tid, lane, wn);
    {
        float* og = out + ((size_t)((b * Cn + c) * Hn + h0)) * Wn;
        #pragma unroll
        for (int mt = 0; mt < 2; ++mt)
            #pragma unroll
            for (int nt = 0; nt < 4; ++nt) {
                const int rA = rAb + mt * 16, rB = rA + 8;
                const int cb = cb0 + nt * 8;
                float2 pA = ldsf2(ls_addr(sm, rA, cb, m));
                float2 pB = ldsf2(ls_addr(sm, rB, cb, m));
                const size_t ba  = bias_row + (size_t)rA * Wn + cb + m * 2;
                const size_t bbo = bias_row + (size_t)rB * Wn + cb + m * 2;
                float2 bvA = *reinterpret_cast<const float2*>(vb + ba);
                float2 bvB = *reinterpret_cast<const float2*>(vb + bbo);
                const float* a4 = acc + mt * 16 + nt * 4;
                float2 oA, oB;
                oA.x = pA.x * (a4[0] + bvA.x);
                oA.y = pA.y * (a4[1] + bvA.y);
                oB.x = pB.x * (a4[2] + bvB.x);
                oB.y = pB.y * (a4[3] + bvB.y);
                *reinterpret_cast<float2*>(og + (size_t)rA * Wn + cb + m * 2) = oA;
                *reinterpret_cast<float2*>(og + (size_t)rB * Wn + cb + m * 2) = oB;
            }
    }
}

extern "C" void kernel_launch(void* const* d_in, const int* in_sizes, int n_in,
                              void* d_out, int out_size) {
    const float* x  = (const float*)d_in[0];
    const float* qw = (const float*)d_in[1];
    const float* kw = (const float*)d_in[2];
    const float* vw = (const float*)d_in[3];
    const float* qb = (const float*)d_in[4];
    const float* kb = (const float*)d_in[5];
    const float* vb = (const float*)d_in[6];
    float* out = (float*)d_out;

    // 1) pre-split weights into fp16 hi/lo stage images
    wsplit_kernel<<<dim3(16, 64, 3), 256>>>(qw, kw, vw);

    // 2) main fused kernel: 2 CTAs/SM
    cudaFuncSetAttribute(axile_attn_f16,
                         cudaFuncAttributeMaxDynamicSharedMemorySize, SM_TOTAL);
    dim3 grid((Hn / TM) * Bn, Cn);   // 64 x 64 = 4096 CTAs
    axile_attn_f16<<<grid, NTH, SM_TOTAL>>>(x, qb, kb, vb, out);
}